// round 1
// baseline (speedup 1.0000x reference)
#include <cuda_runtime.h>
#include <math.h>

#define BB 64
#define NN 1024
#define DD 512
#define KK 64
#define KG 80
#define ROWS (BB*NN)   // 65536

// Scratch (static device allocations — allowed)
__device__ float g_cs[DD*KK];          // scaled clusters, first 64 cols only
__device__ float g_assign[ROWS*KK];    // softmax assignment   (16.8 MB)
__device__ float g_vlad[BB*DD*KK];     // raw einsum result    (8.4 MB)

// ---------------------------------------------------------------------------
// K1: fold BN scale into cluster columns (only the K real clusters matter:
// ghosts are dropped before softmax in the reference, and the BN shift is
// never applied).
// ---------------------------------------------------------------------------
__global__ void k_prep(const float* __restrict__ clusters,
                       const float* __restrict__ bn_w,
                       const float* __restrict__ bn_var) {
    int i = blockIdx.x * 256 + threadIdx.x;       // grid covers DD*KK exactly
    int d = i >> 6;
    int k = i & 63;
    float s = bn_w[k] * rsqrtf(bn_var[k] + 1e-5f);
    g_cs[i] = clusters[d * KG + k] * s;
}

// ---------------------------------------------------------------------------
// K2: logits GEMM [65536,512]x[512,64] fused with row softmax.
// 128 threads/block, 1 thread = 1 row, 64 fp32 accumulators.
// ---------------------------------------------------------------------------
__global__ __launch_bounds__(128) void k_assign(const float* __restrict__ x) {
    __shared__ float xs[128][33];     // padded: bank (tid+dd)%32, conflict-free
    __shared__ float cs[32][64];      // broadcast reads

    const int tid  = threadIdx.x;
    const int warp = tid >> 5;
    const int lane = tid & 31;
    const long rowbase = (long)blockIdx.x * 128;

    float acc[64];
#pragma unroll
    for (int k = 0; k < 64; k++) acc[k] = 0.f;

    for (int d0 = 0; d0 < DD; d0 += 32) {
        // x tile: each warp loads rows warp, warp+4, ... (coalesced 128B)
#pragma unroll
        for (int r = warp; r < 128; r += 4)
            xs[r][lane] = x[(rowbase + r) * DD + d0 + lane];
        // cluster tile (coalesced)
#pragma unroll
        for (int i = tid; i < 32 * 64; i += 128)
            cs[i >> 6][i & 63] = g_cs[(d0 + (i >> 6)) * KK + (i & 63)];
        __syncthreads();

#pragma unroll
        for (int dd = 0; dd < 32; dd++) {
            const float xv = xs[tid][dd];
#pragma unroll
            for (int k = 0; k < 64; k++)
                acc[k] = fmaf(xv, cs[dd][k], acc[k]);
        }
        __syncthreads();
    }

    // softmax over the 64 real clusters
    float m = acc[0];
#pragma unroll
    for (int k = 1; k < 64; k++) m = fmaxf(m, acc[k]);
    float s = 0.f;
#pragma unroll
    for (int k = 0; k < 64; k++) { acc[k] = __expf(acc[k] - m); s += acc[k]; }
    const float inv = 1.f / s;
#pragma unroll
    for (int k = 0; k < 64; k++) acc[k] *= inv;

    float4* outp = (float4*)&g_assign[(rowbase + tid) * KK];
#pragma unroll
    for (int k = 0; k < 64; k += 4)
        outp[k >> 2] = make_float4(acc[k], acc[k + 1], acc[k + 2], acc[k + 3]);
}

// ---------------------------------------------------------------------------
// K3: per-batch einsum  vlad[b,d,k] = sum_n a[b,n,k]*x[b,n,d]
//     == X^T @ A : [512,1024]@[1024,64] per batch.
// Block = 64x64 output tile, 256 threads, 4x4 register blocking.
// ---------------------------------------------------------------------------
__global__ __launch_bounds__(256) void k_vlad(const float* __restrict__ x) {
    __shared__ float xs[16][68];   // row stride 68 floats: 16B-aligned rows
    __shared__ float as[16][68];

    const int b  = blockIdx.y;
    const int d0 = blockIdx.x * 64;
    const int tid = threadIdx.x;
    const int tx = tid & 15;       // k sub-tile
    const int ty = tid >> 4;       // d sub-tile

    const float* xb = x        + (long)b * NN * DD;
    const float* ab = g_assign + (long)b * NN * KK;

    float acc[4][4];
#pragma unroll
    for (int i = 0; i < 4; i++)
#pragma unroll
        for (int j = 0; j < 4; j++) acc[i][j] = 0.f;

    const int ln = tid >> 4;          // 0..15 : row within tile to load
    const int ld = (tid & 15) * 4;    // 0..60 : float4 column

    for (int n0 = 0; n0 < NN; n0 += 16) {
        *(float4*)&xs[ln][ld] = *(const float4*)&xb[(n0 + ln) * DD + d0 + ld];
        *(float4*)&as[ln][ld] = *(const float4*)&ab[(n0 + ln) * KK + ld];
        __syncthreads();

#pragma unroll
        for (int nn = 0; nn < 16; nn++) {
            const float4 xv = *(const float4*)&xs[nn][ty * 4];
            const float4 av = *(const float4*)&as[nn][tx * 4];
            const float xr[4] = {xv.x, xv.y, xv.z, xv.w};
            const float ar[4] = {av.x, av.y, av.z, av.w};
#pragma unroll
            for (int i = 0; i < 4; i++)
#pragma unroll
                for (int j = 0; j < 4; j++)
                    acc[i][j] = fmaf(xr[i], ar[j], acc[i][j]);
        }
        __syncthreads();
    }

    float* vp = g_vlad + ((long)b * DD + d0) * KK;
#pragma unroll
    for (int i = 0; i < 4; i++)
        *(float4*)&vp[(ty * 4 + i) * KK + tx * 4] =
            make_float4(acc[i][0], acc[i][1], acc[i][2], acc[i][3]);
}

// ---------------------------------------------------------------------------
// K4: per-batch epilogue:
//   a_sum[k] = sum_n assignment (deterministic recompute, no atomics)
//   v = vlad_raw - a_sum[k]*clusters2[d,k]
//   intra L2-norm over D, then global L2-norm over D*K
// Block = 1 batch, 512 threads: t%64 = k (coalesced), t/64 = stripe over D/n.
// ---------------------------------------------------------------------------
__global__ __launch_bounds__(512) void k_norm(const float* __restrict__ c2,
                                              float* __restrict__ out) {
    __shared__ float red[512];
    __shared__ float colscale[64];
    __shared__ float ginv_s;

    const int b  = blockIdx.x;
    const int t  = threadIdx.x;
    const int k  = t & 63;
    const int dg = t >> 6;            // 8 stripes

    // --- a_sum[b,k] ---
    const float* abk = g_assign + (long)b * NN * KK;
    float part = 0.f;
    for (int n = dg; n < NN; n += 8) part += abk[n * KK + k];
    red[t] = part;
    __syncthreads();
    float asum = 0.f;
#pragma unroll
    for (int g = 0; g < 8; g++) asum += red[g * 64 + k];
    __syncthreads();

    // --- residual + intra-norm sumsq ---
    const float* vb = g_vlad + (long)b * DD * KK;
    float* ob = out + (long)b * DD * KK;
    float local = 0.f;
    for (int d = dg; d < DD; d += 8) {
        const float v = vb[d * KK + k] - asum * c2[d * KK + k];
        ob[d * KK + k] = v;
        local += v * v;
    }
    red[t] = local;
    __syncthreads();

    if (t < 64) {
        float ss = 0.f;
#pragma unroll
        for (int g = 0; g < 8; g++) ss += red[g * 64 + t];
        const float n  = sqrtf(ss);
        const float cs = 1.f / fmaxf(n, 1e-12f);
        colscale[t] = cs;
        const float nu = n * cs;      // normalized column norm (≈1)
        red[t] = nu * nu;
    }
    __syncthreads();
    if (t == 0) {
        float g = 0.f;
#pragma unroll
        for (int kk = 0; kk < 64; kk++) g += red[kk];
        ginv_s = 1.f / fmaxf(sqrtf(g), 1e-12f);
    }
    __syncthreads();

    const float sc = colscale[k] * ginv_s;
    for (int d = dg; d < DD; d += 8)
        ob[d * KK + k] *= sc;
}

// ---------------------------------------------------------------------------
extern "C" void kernel_launch(void* const* d_in, const int* in_sizes, int n_in,
                              void* d_out, int out_size) {
    const float* x        = (const float*)d_in[0];  // [64,1024,512]
    const float* clusters = (const float*)d_in[1];  // [512,80]
    const float* bn_w     = (const float*)d_in[2];  // [80]
    // d_in[3] bn_bias, d_in[4] bn_mean: computed-but-unused in reference
    const float* bn_var   = (const float*)d_in[5];  // [80]
    const float* c2       = (const float*)d_in[6];  // [1,512,64]
    float* out = (float*)d_out;

    k_prep<<<(DD * KK) / 256, 256>>>(clusters, bn_w, bn_var);
    k_assign<<<ROWS / 128, 128>>>(x);
    dim3 g3(DD / 64, BB);
    k_vlad<<<g3, 256>>>(x);
    k_norm<<<BB, 512>>>(c2, out);
}